// round 3
// baseline (speedup 1.0000x reference)
#include <cuda_runtime.h>
#include <cuda_bf16.h>
#include <cstdint>

// ---------------- problem constants ----------------
#define N0v 200000
#define N1v 100000
#define N2v 80000
#define K5v 125
#define K3v 27
#define M1v 20000
#define M2v 20000
#define M3v 30000
#define M4v 20000
#define EPSv 1e-5f

// ---------------- scratch (device globals; no allocs allowed) ----------------
__device__ float g_buf1[N1v * 32];
__device__ float g_buf2[N1v * 32];
__device__ float g_buf3[N2v * 64];
__device__ float g_buf4[N2v * 128];
__device__ float g_buf5[N2v * 256];
__device__ float g_sum[256];
__device__ float g_sumsq[256];

// fragment-packed tf32-split weights.
// per layer floats = 2 * K * CIN * COUT   (hi+lo interleaved in float4 frags)
#define OFF_W1B 0
#define OFF_W1C 256000
#define OFF_W2  512000
#define OFF_W3A 622592
#define OFF_W3B 1064960
#define WFRAG_TOTAL 2834432
__device__ __align__(16) float g_wfrag[WFRAG_TOTAL];

// ---------------- small helpers ----------------
__device__ __forceinline__ void red4(float* p, float a, float b, float c, float d) {
    asm volatile("red.global.add.v4.f32 [%0], {%1,%2,%3,%4};"
                 :: "l"(p), "f"(a), "f"(b), "f"(c), "f"(d) : "memory");
}
__device__ __forceinline__ void red2(float* p, float a, float b) {
    asm volatile("red.global.add.v2.f32 [%0], {%1,%2};"
                 :: "l"(p), "f"(a), "f"(b) : "memory");
}
__device__ __forceinline__ float tf32_hi(float v) {
    uint32_t u;
    asm("cvt.rna.tf32.f32 %0, %1;" : "=r"(u) : "f"(v));
    return __uint_as_float(u);
}

// m16n8k8 tf32 mma: D += A * B  (row.col, f32 accum)
__device__ __forceinline__ void mma8(float* d, const float* a, float b0, float b1) {
    asm volatile(
        "mma.sync.aligned.m16n8k8.row.col.f32.tf32.tf32.f32 "
        "{%0,%1,%2,%3}, {%4,%5,%6,%7}, {%8,%9}, {%0,%1,%2,%3};"
        : "+f"(d[0]), "+f"(d[1]), "+f"(d[2]), "+f"(d[3])
        : "r"(__float_as_uint(a[0])), "r"(__float_as_uint(a[1])),
          "r"(__float_as_uint(a[2])), "r"(__float_as_uint(a[3])),
          "r"(__float_as_uint(b0)), "r"(__float_as_uint(b1)));
}

// ---------------- weight prep: transpose + tf32 split + fragment pack ----------------
// frag float4 index = ((k*(CIN/8) + ci/8)*(COUT/8) + co/8)*32 + lane,
//   lane = (co%8)*4 + (ci%4);  components: [b0_hi, b1_hi, b0_lo, b1_lo],
//   b0 covers ci%8 in 0..3, b1 covers ci%8 in 4..7.
__global__ void wprep_frag(const float* __restrict__ w, float* __restrict__ frag,
                           int CIN, int COUT, int total) {
    int e = blockIdx.x * blockDim.x + threadIdx.x;
    if (e >= total) return;
    int per = CIN * COUT;
    int k = e / per;
    int r = e - k * per;
    int ci = r / COUT;
    int co = r - ci * COUT;
    float v = w[e];
    float h = tf32_hi(v);
    float l = v - h;
    int lane = ((co & 7) << 2) | (ci & 3);
    size_t f4 = (((size_t)k * (CIN >> 3) + (ci >> 3)) * (COUT >> 3) + (co >> 3)) * 32 + lane;
    int comp = (ci >> 2) & 1;
    frag[f4 * 4 + comp] = h;
    frag[f4 * 4 + comp + 2] = l;
}

// ---------------- conv1a: CIN=1 special case (fp32 scalar) ----------------
__global__ void conv1a_kernel(const float* __restrict__ x, const float* __restrict__ w,
                              const int* __restrict__ in_idx, const int* __restrict__ out_idx,
                              float* __restrict__ out, int total, int M) {
    int gid = blockIdx.x * blockDim.x + threadIdx.x;
    int pair = gid >> 3;
    if (pair >= total) return;
    int g = gid & 7;
    int k = pair / M;
    float v = x[in_idx[pair]];
    float4 wv = *reinterpret_cast<const float4*>(w + k * 32 + g * 4);
    float* dst = out + (size_t)out_idx[pair] * 32 + g * 4;
    red4(dst, v * wv.x, v * wv.y, v * wv.z, v * wv.w);
}

// ---------------- tf32x3 gather-MMA-scatter ----------------
// BM=128 kernel-map entries, 8 warps (each 16 rows), BN cols, K chunks of 32.
template<int CIN, int COUT, int BN>
__global__ __launch_bounds__(256)
void spconv_mma(const float* __restrict__ feats, const float* __restrict__ wfrag,
                const int* __restrict__ in_idx, const int* __restrict__ out_idx,
                float* __restrict__ out, int M) {
    constexpr int NT  = BN / 8;       // n tiles this CTA
    constexpr int NTG = COUT / 8;     // n tiles globally per k8
    constexpr int NCH = CIN / 32;     // k chunks

    __shared__ float As_h[128][36];
    __shared__ float As_l[128][36];
    __shared__ int rows[128];

    const int k   = blockIdx.z;
    const int m0  = blockIdx.x * 128;
    const int n0  = blockIdx.y * BN;
    const int tid = threadIdx.x;
    const int wid = tid >> 5;
    const int lane = tid & 31;

    if (tid < 128) {
        int m = m0 + tid;
        rows[tid] = (m < M) ? in_idx[k * M + m] : -1;
    }
    __syncthreads();
    const int frow = rows[tid >> 1];
    const int mrow = tid >> 1;
    const int half = (tid & 1) * 16;

    float acc[NT][4];
#pragma unroll
    for (int nt = 0; nt < NT; nt++) {
        acc[nt][0] = 0.f; acc[nt][1] = 0.f; acc[nt][2] = 0.f; acc[nt][3] = 0.f;
    }

    const float4* wbase = reinterpret_cast<const float4*>(wfrag)
                        + ((size_t)k * (CIN >> 3)) * NTG * 32;

    const int gr = lane >> 2;   // group row
    const int gc = lane & 3;    // group col

    for (int c = 0; c < NCH; c++) {
        if (c) __syncthreads();
        // gather A chunk (2 threads per row, 16 floats each), split hi/lo
        {
            float* dh = &As_h[mrow][half];
            float* dl = &As_l[mrow][half];
            if (frow >= 0) {
                const float4* src = reinterpret_cast<const float4*>(
                    feats + (size_t)frow * CIN + c * 32 + half);
#pragma unroll
                for (int j = 0; j < 4; j++) {
                    float4 v = src[j];
                    float4 h, l;
                    h.x = tf32_hi(v.x); l.x = v.x - h.x;
                    h.y = tf32_hi(v.y); l.y = v.y - h.y;
                    h.z = tf32_hi(v.z); l.z = v.z - h.z;
                    h.w = tf32_hi(v.w); l.w = v.w - h.w;
                    *reinterpret_cast<float4*>(dh + j * 4) = h;
                    *reinterpret_cast<float4*>(dl + j * 4) = l;
                }
            } else {
                float4 z = make_float4(0.f, 0.f, 0.f, 0.f);
#pragma unroll
                for (int j = 0; j < 4; j++) {
                    *reinterpret_cast<float4*>(dh + j * 4) = z;
                    *reinterpret_cast<float4*>(dl + j * 4) = z;
                }
            }
        }
        __syncthreads();

#pragma unroll
        for (int s = 0; s < 4; s++) {
            const int kk = s * 8;
            const int r0 = wid * 16 + gr;
            float aH[4], aL[4];
            aH[0] = As_h[r0][kk + gc];
            aH[1] = As_h[r0 + 8][kk + gc];
            aH[2] = As_h[r0][kk + gc + 4];
            aH[3] = As_h[r0 + 8][kk + gc + 4];
            aL[0] = As_l[r0][kk + gc];
            aL[1] = As_l[r0 + 8][kk + gc];
            aL[2] = As_l[r0][kk + gc + 4];
            aL[3] = As_l[r0 + 8][kk + gc + 4];

            const float4* wrow = wbase + ((size_t)(c * 4 + s) * NTG + (n0 >> 3)) * 32 + lane;
#pragma unroll
            for (int nt = 0; nt < NT; nt++) {
                float4 b = wrow[nt * 32];
                mma8(acc[nt], aH, b.x, b.y);   // hi*hi
                mma8(acc[nt], aL, b.x, b.y);   // lo*hi
                mma8(acc[nt], aH, b.z, b.w);   // hi*lo
            }
        }
    }

    // scatter: c0,c1 -> row gr; c2,c3 -> row gr+8, cols (lane%4)*2
    const int mA = m0 + wid * 16 + gr;
    const int mB = mA + 8;
    const int oA = (mA < M) ? out_idx[k * M + mA] : -1;
    const int oB = (mB < M) ? out_idx[k * M + mB] : -1;
    const int colb = n0 + gc * 2;
    float* dA = out + (oA >= 0 ? (size_t)oA * COUT : 0) + colb;
    float* dB = out + (oB >= 0 ? (size_t)oB * COUT : 0) + colb;
#pragma unroll
    for (int nt = 0; nt < NT; nt++) {
        if (oA >= 0) red2(dA + nt * 8, acc[nt][0], acc[nt][1]);
        if (oB >= 0) red2(dB + nt * 8, acc[nt][2], acc[nt][3]);
    }
}

// ---------------- elementwise / BN kernels ----------------
__global__ void relu_kernel(float* __restrict__ x, int n4) {
    int i = blockIdx.x * blockDim.x + threadIdx.x;
    if (i >= n4) return;
    float4 v = reinterpret_cast<float4*>(x)[i];
    v.x = fmaxf(v.x, 0.f); v.y = fmaxf(v.y, 0.f);
    v.z = fmaxf(v.z, 0.f); v.w = fmaxf(v.w, 0.f);
    reinterpret_cast<float4*>(x)[i] = v;
}

__global__ void zero_stats_kernel() {
    g_sum[threadIdx.x] = 0.f;
    g_sumsq[threadIdx.x] = 0.f;
}

__global__ void bn_stats_kernel(const float* __restrict__ x, int total, int cmask) {
    __shared__ float ssum[256], ssq[256];
    for (int c = threadIdx.x; c < 256; c += blockDim.x) { ssum[c] = 0.f; ssq[c] = 0.f; }
    __syncthreads();
    for (int e = blockIdx.x * blockDim.x + threadIdx.x; e < total; e += gridDim.x * blockDim.x) {
        float v = x[e];
        int c = e & cmask;
        atomicAdd(&ssum[c], v);
        atomicAdd(&ssq[c], v * v);
    }
    __syncthreads();
    for (int c = threadIdx.x; c <= cmask; c += blockDim.x) {
        atomicAdd(&g_sum[c], ssum[c]);
        atomicAdd(&g_sumsq[c], ssq[c]);
    }
}

__global__ void bn_relu_kernel(const float* __restrict__ x, float* __restrict__ y,
                               const float* __restrict__ gg, const float* __restrict__ bb,
                               float invN, int total, int cmask) {
    int e = blockIdx.x * blockDim.x + threadIdx.x;
    if (e >= total) return;
    int c = e & cmask;
    float mean = g_sum[c] * invN;
    float var  = g_sumsq[c] * invN - mean * mean;
    float s = rsqrtf(var + EPSv) * gg[c];
    float v = (x[e] - mean) * s + bb[c];
    y[e] = fmaxf(v, 0.f);
}

// ---------------- orchestration ----------------
extern "C" void kernel_launch(void* const* d_in, const int* in_sizes, int n_in,
                              void* d_out, int out_size) {
    const float* x_feats = (const float*)d_in[0];
    const float* w1a = (const float*)d_in[1];
    const float* w1b = (const float*)d_in[2];
    const float* w1c = (const float*)d_in[3];
    const float* w2  = (const float*)d_in[4];
    const float* w3a = (const float*)d_in[5];
    const float* w3b = (const float*)d_in[6];
    const float* bn1b_g = (const float*)d_in[7];
    const float* bn1b_b = (const float*)d_in[8];
    const float* bn1c_g = (const float*)d_in[9];
    const float* bn1c_b = (const float*)d_in[10];
    const float* bn3a_g = (const float*)d_in[11];
    const float* bn3a_b = (const float*)d_in[12];
    const float* bn3b_g = (const float*)d_in[13];
    const float* bn3b_b = (const float*)d_in[14];
    const int* km1a_in  = (const int*)d_in[15];
    const int* km1a_out = (const int*)d_in[16];
    const int* km1b_in  = (const int*)d_in[17];
    const int* km1b_out = (const int*)d_in[18];
    const int* km1c_in  = (const int*)d_in[19];
    const int* km1c_out = (const int*)d_in[20];
    const int* km2_in   = (const int*)d_in[21];
    const int* km2_out  = (const int*)d_in[22];
    const int* km3a_in  = (const int*)d_in[23];
    const int* km3a_out = (const int*)d_in[24];
    const int* km3b_in  = (const int*)d_in[25];
    const int* km3b_out = (const int*)d_in[26];

    float* out = (float*)d_out;
    float* x_e1 = out;
    float* x_e2 = out + (size_t)N1v * 32;

    float *buf1, *buf2, *buf3, *buf4, *buf5, *wf;
    cudaGetSymbolAddress((void**)&buf1, g_buf1);
    cudaGetSymbolAddress((void**)&buf2, g_buf2);
    cudaGetSymbolAddress((void**)&buf3, g_buf3);
    cudaGetSymbolAddress((void**)&buf4, g_buf4);
    cudaGetSymbolAddress((void**)&buf5, g_buf5);
    cudaGetSymbolAddress((void**)&wf, g_wfrag);

    // ---- weight prep (fragment pack + tf32 split) ----
    {
        int t1 = K5v * 32 * 32, t2 = K3v * 32 * 64, t3 = K3v * 64 * 128, t4 = K3v * 128 * 256;
        wprep_frag<<<(t1 + 255) / 256, 256>>>(w1b, wf + OFF_W1B, 32, 32, t1);
        wprep_frag<<<(t1 + 255) / 256, 256>>>(w1c, wf + OFF_W1C, 32, 32, t1);
        wprep_frag<<<(t2 + 255) / 256, 256>>>(w2,  wf + OFF_W2,  32, 64, t2);
        wprep_frag<<<(t3 + 255) / 256, 256>>>(w3a, wf + OFF_W3A, 64, 128, t3);
        wprep_frag<<<(t4 + 255) / 256, 256>>>(w3b, wf + OFF_W3B, 128, 256, t4);
    }

    const int STATS_GRID = 2048;

    // ---- enc1a: conv(1->32, k5) + relu ----
    cudaMemsetAsync(buf1, 0, (size_t)N1v * 32 * sizeof(float), 0);
    {
        int total = K5v * M1v;
        conv1a_kernel<<<(total * 8 + 255) / 256, 256>>>(x_feats, w1a, km1a_in, km1a_out, buf1, total, M1v);
        relu_kernel<<<(N1v * 32 / 4 + 255) / 256, 256>>>(buf1, N1v * 32 / 4);
    }

    // ---- enc1b: conv(32->32, k5) + BN + relu ----
    cudaMemsetAsync(buf2, 0, (size_t)N1v * 32 * sizeof(float), 0);
    spconv_mma<32, 32, 32><<<dim3((M2v + 127) / 128, 1, K5v), 256>>>(
        buf1, wf + OFF_W1B, km1b_in, km1b_out, buf2, M2v);
    zero_stats_kernel<<<1, 256>>>();
    bn_stats_kernel<<<STATS_GRID, 256>>>(buf2, N1v * 32, 31);
    bn_relu_kernel<<<(N1v * 32 + 255) / 256, 256>>>(buf2, buf1, bn1b_g, bn1b_b, 1.0f / N1v, N1v * 32, 31);

    // ---- enc1c: conv(32->32, k5) + BN + relu -> x_e1 ----
    cudaMemsetAsync(buf2, 0, (size_t)N1v * 32 * sizeof(float), 0);
    spconv_mma<32, 32, 32><<<dim3((M2v + 127) / 128, 1, K5v), 256>>>(
        buf1, wf + OFF_W1C, km1c_in, km1c_out, buf2, M2v);
    zero_stats_kernel<<<1, 256>>>();
    bn_stats_kernel<<<STATS_GRID, 256>>>(buf2, N1v * 32, 31);
    bn_relu_kernel<<<(N1v * 32 + 255) / 256, 256>>>(buf2, x_e1, bn1c_g, bn1c_b, 1.0f / N1v, N1v * 32, 31);

    // ---- conv2: conv(32->64, k3), no activation ----
    cudaMemsetAsync(buf3, 0, (size_t)N2v * 64 * sizeof(float), 0);
    spconv_mma<32, 64, 64><<<dim3((M3v + 127) / 128, 1, K3v), 256>>>(
        x_e1, wf + OFF_W2, km2_in, km2_out, buf3, M3v);

    // ---- enc2a: conv(64->128, k3) + BN + relu ----
    cudaMemsetAsync(buf4, 0, (size_t)N2v * 128 * sizeof(float), 0);
    spconv_mma<64, 128, 128><<<dim3((M4v + 127) / 128, 1, K3v), 256>>>(
        buf3, wf + OFF_W3A, km3a_in, km3a_out, buf4, M4v);
    zero_stats_kernel<<<1, 256>>>();
    bn_stats_kernel<<<STATS_GRID, 256>>>(buf4, N2v * 128, 127);
    bn_relu_kernel<<<(N2v * 128 + 255) / 256, 256>>>(buf4, buf4, bn3a_g, bn3a_b, 1.0f / N2v, N2v * 128, 127);

    // ---- enc2b: conv(128->256, k3) + BN + relu -> x_e2 ----
    cudaMemsetAsync(buf5, 0, (size_t)N2v * 256 * sizeof(float), 0);
    spconv_mma<128, 256, 128><<<dim3((M4v + 127) / 128, 2, K3v), 256>>>(
        buf4, wf + OFF_W3B, km3b_in, km3b_out, buf5, M4v);
    zero_stats_kernel<<<1, 256>>>();
    bn_stats_kernel<<<STATS_GRID, 256>>>(buf5, N2v * 256, 255);
    bn_relu_kernel<<<(N2v * 256 + 255) / 256, 256>>>(buf5, x_e2, bn3b_g, bn3b_b, 1.0f / N2v, N2v * 256, 255);
}

// round 4
// speedup vs baseline: 1.4393x; 1.4393x over previous
#include <cuda_runtime.h>
#include <cuda_bf16.h>
#include <cstdint>

// ---------------- problem constants ----------------
#define N0v 200000
#define N1v 100000
#define N2v 80000
#define K5v 125
#define K3v 27
#define M1v 20000
#define M2v 20000
#define M3v 30000
#define M4v 20000
#define EPSv 1e-5f

// ---------------- scratch (device globals; no allocs allowed) ----------------
__device__ float g_buf1[N1v * 32];
__device__ float g_buf2[N1v * 32];
__device__ float g_buf3[N2v * 64];
__device__ float g_buf4[N2v * 128];
__device__ float g_buf5[N2v * 256];
__device__ float g_sum[256];
__device__ float g_sumsq[256];

// fragment-packed bf16-split weights (uint4 per lane: b0_hi,b1_hi,b0_lo,b1_lo)
// uint4 count per layer = K*CIN*COUT/4
#define OFF_W1B 0
#define OFF_W1C 32000
#define OFF_W2  64000
#define OFF_W3A 77824
#define OFF_W3B 133120
#define WFRAG_U4 354304
__device__ __align__(16) __nv_bfloat16 g_wfrag[WFRAG_U4 * 8];

// ---------------- small helpers ----------------
__device__ __forceinline__ void red4(float* p, float a, float b, float c, float d) {
    asm volatile("red.global.add.v4.f32 [%0], {%1,%2,%3,%4};"
                 :: "l"(p), "f"(a), "f"(b), "f"(c), "f"(d) : "memory");
}
__device__ __forceinline__ void red2(float* p, float a, float b) {
    asm volatile("red.global.add.v2.f32 [%0], {%1,%2};"
                 :: "l"(p), "f"(a), "f"(b) : "memory");
}

// bf16 m16n8k16 mma: D += A * B (row.col, f32 accum)
__device__ __forceinline__ void mma16(float* d, const uint32_t* a, uint32_t b0, uint32_t b1) {
    asm volatile(
        "mma.sync.aligned.m16n8k16.row.col.f32.bf16.bf16.f32 "
        "{%0,%1,%2,%3}, {%4,%5,%6,%7}, {%8,%9}, {%0,%1,%2,%3};"
        : "+f"(d[0]), "+f"(d[1]), "+f"(d[2]), "+f"(d[3])
        : "r"(a[0]), "r"(a[1]), "r"(a[2]), "r"(a[3]), "r"(b0), "r"(b1));
}

// ---------------- weight prep: transpose + bf16 split + fragment pack ----------------
// frag uint4 index = ((k*(CIN/16) + ci/16)*(COUT/8) + co/8)*32 + lane
//   lane = (co%8)*4 + ((ci%8)>>1)
//   bf16 slots within uint4 (as bf16[8]): hi at ((ci%16)>>3)*2 + (ci&1), lo at +4
__global__ void wprep_frag(const float* __restrict__ w, __nv_bfloat16* __restrict__ frag,
                           int CIN, int COUT, int total) {
    int e = blockIdx.x * blockDim.x + threadIdx.x;
    if (e >= total) return;
    int per = CIN * COUT;
    int k = e / per;
    int r = e - k * per;
    int ci = r / COUT;
    int co = r - ci * COUT;
    float v = w[e];
    __nv_bfloat16 h = __float2bfloat16(v);
    __nv_bfloat16 l = __float2bfloat16(v - __bfloat162float(h));
    int lane = ((co & 7) << 2) | ((ci & 7) >> 1);
    size_t f4 = (((size_t)k * (CIN >> 4) + (ci >> 4)) * (COUT >> 3) + (co >> 3)) * 32 + lane;
    int within = ci & 15;
    int slot = ((within >> 3) << 1) | (within & 1);
    frag[f4 * 8 + slot] = h;
    frag[f4 * 8 + 4 + slot] = l;
}

// ---------------- conv1a: CIN=1 special case (fp32 scalar) ----------------
__global__ void conv1a_kernel(const float* __restrict__ x, const float* __restrict__ w,
                              const int* __restrict__ in_idx, const int* __restrict__ out_idx,
                              float* __restrict__ out, int total, int M) {
    int gid = blockIdx.x * blockDim.x + threadIdx.x;
    int pair = gid >> 3;
    if (pair >= total) return;
    int g = gid & 7;
    int k = pair / M;
    float v = x[in_idx[pair]];
    float4 wv = *reinterpret_cast<const float4*>(w + k * 32 + g * 4);
    float* dst = out + (size_t)out_idx[pair] * 32 + g * 4;
    red4(dst, v * wv.x, v * wv.y, v * wv.z, v * wv.w);
}

// ---------------- bf16x3 gather-MMA-scatter ----------------
// BM=128 rows (8 warps x 16 rows), BN cols, K chunks of 32 (=2 k16 steps).
template<int CIN, int COUT, int BN>
__global__ __launch_bounds__(256)
void spconv_mma(const float* __restrict__ feats, const __nv_bfloat16* __restrict__ wfrag,
                const int* __restrict__ in_idx, const int* __restrict__ out_idx,
                float* __restrict__ out, int M) {
    constexpr int NT  = BN / 8;
    constexpr int NTG = COUT / 8;
    constexpr int NCH = CIN / 32;

    __shared__ uint32_t As_h[128][20];   // bf16x2 words, stride 20 => conflict-free frags
    __shared__ uint32_t As_l[128][20];
    __shared__ int rows[128];

    const int k    = blockIdx.z;
    const int m0   = blockIdx.x * 128;
    const int n0   = blockIdx.y * BN;
    const int tid  = threadIdx.x;
    const int wid  = tid >> 5;
    const int lane = tid & 31;

    if (tid < 128) {
        int m = m0 + tid;
        rows[tid] = (m < M) ? in_idx[k * M + m] : -1;
    }
    __syncthreads();
    const int mrow = tid >> 1;
    const int frow = rows[mrow];
    const int half = tid & 1;     // which 16-float half of the 32-k chunk

    float acc[NT][4];
#pragma unroll
    for (int nt = 0; nt < NT; nt++) {
        acc[nt][0] = 0.f; acc[nt][1] = 0.f; acc[nt][2] = 0.f; acc[nt][3] = 0.f;
    }

    const uint4* wbase = reinterpret_cast<const uint4*>(wfrag)
                       + ((size_t)k * (CIN >> 4)) * NTG * 32;

    const int gr = lane >> 2;
    const int gc = lane & 3;
    const int r0 = wid * 16 + gr;

    for (int c = 0; c < NCH; c++) {
        if (c) __syncthreads();
        // gather A chunk: 2 threads per row, 16 floats each, bf16 hi/lo split
        {
            uint32_t* dh = &As_h[mrow][half * 8];
            uint32_t* dl = &As_l[mrow][half * 8];
            if (frow >= 0) {
                const float4* src = reinterpret_cast<const float4*>(
                    feats + (size_t)frow * CIN + c * 32 + half * 16);
#pragma unroll
                for (int j = 0; j < 4; j++) {
                    float4 v = src[j];
                    __nv_bfloat162 h01 = __floats2bfloat162_rn(v.x, v.y);
                    __nv_bfloat162 h23 = __floats2bfloat162_rn(v.z, v.w);
                    __nv_bfloat162 l01 = __floats2bfloat162_rn(
                        v.x - __bfloat162float(h01.x), v.y - __bfloat162float(h01.y));
                    __nv_bfloat162 l23 = __floats2bfloat162_rn(
                        v.z - __bfloat162float(h23.x), v.w - __bfloat162float(h23.y));
                    dh[j * 2]     = *reinterpret_cast<uint32_t*>(&h01);
                    dh[j * 2 + 1] = *reinterpret_cast<uint32_t*>(&h23);
                    dl[j * 2]     = *reinterpret_cast<uint32_t*>(&l01);
                    dl[j * 2 + 1] = *reinterpret_cast<uint32_t*>(&l23);
                }
            } else {
#pragma unroll
                for (int j = 0; j < 8; j++) { dh[j] = 0u; dl[j] = 0u; }
            }
        }
        __syncthreads();

#pragma unroll
        for (int s = 0; s < 2; s++) {          // two k16 steps per 32-chunk
            const int kb = s * 8;
            uint32_t aH[4], aL[4];
            aH[0] = As_h[r0][kb + gc];
            aH[1] = As_h[r0 + 8][kb + gc];
            aH[2] = As_h[r0][kb + 4 + gc];
            aH[3] = As_h[r0 + 8][kb + 4 + gc];
            aL[0] = As_l[r0][kb + gc];
            aL[1] = As_l[r0 + 8][kb + gc];
            aL[2] = As_l[r0][kb + 4 + gc];
            aL[3] = As_l[r0 + 8][kb + 4 + gc];

            const uint4* wrow = wbase + ((size_t)(c * 2 + s) * NTG + (n0 >> 3)) * 32 + lane;
#pragma unroll
            for (int nt = 0; nt < NT; nt++) {
                uint4 b = wrow[nt * 32];
                mma16(acc[nt], aH, b.x, b.y);   // hi*hi
                mma16(acc[nt], aL, b.x, b.y);   // lo*hi
                mma16(acc[nt], aH, b.z, b.w);   // hi*lo
            }
        }
    }

    // scatter: c0,c1 -> row r0, cols 2gc..; c2,c3 -> row r0+8
    const int mA = m0 + r0;
    const int mB = mA + 8;
    const int oA = (mA < M) ? out_idx[k * M + mA] : -1;
    const int oB = (mB < M) ? out_idx[k * M + mB] : -1;
    const int colb = n0 + gc * 2;
    float* dA = out + (oA >= 0 ? (size_t)oA * COUT : 0) + colb;
    float* dB = out + (oB >= 0 ? (size_t)oB * COUT : 0) + colb;
#pragma unroll
    for (int nt = 0; nt < NT; nt++) {
        if (oA >= 0) red2(dA + nt * 8, acc[nt][0], acc[nt][1]);
        if (oB >= 0) red2(dB + nt * 8, acc[nt][2], acc[nt][3]);
    }
}

// ---------------- elementwise / BN kernels ----------------
__global__ void relu_kernel(float* __restrict__ x, int n4) {
    int i = blockIdx.x * blockDim.x + threadIdx.x;
    if (i >= n4) return;
    float4 v = reinterpret_cast<float4*>(x)[i];
    v.x = fmaxf(v.x, 0.f); v.y = fmaxf(v.y, 0.f);
    v.z = fmaxf(v.z, 0.f); v.w = fmaxf(v.w, 0.f);
    reinterpret_cast<float4*>(x)[i] = v;
}

__global__ void zero_stats_kernel() {
    g_sum[threadIdx.x] = 0.f;
    g_sumsq[threadIdx.x] = 0.f;
}

// atomic-free per-thread channel accumulation
template<int C>
__global__ void bn_stats2(const float* __restrict__ x, int rows) {
    constexpr int RPB = 256 / C;
    const int c = threadIdx.x & (C - 1);
    const int rsub = threadIdx.x / C;
    float s = 0.f, q = 0.f;
    for (int r = blockIdx.x * RPB + rsub; r < rows; r += gridDim.x * RPB) {
        float v = x[(size_t)r * C + c];
        s += v; q += v * v;
    }
    __shared__ float ss[256], sq[256];
    ss[threadIdx.x] = s; sq[threadIdx.x] = q;
    __syncthreads();
    if (threadIdx.x < C) {
        for (int j = threadIdx.x + C; j < 256; j += C) { s += ss[j]; q += sq[j]; }
        atomicAdd(&g_sum[c], s);
        atomicAdd(&g_sumsq[c], q);
    }
}

__global__ void bn_relu_kernel(const float* __restrict__ x, float* __restrict__ y,
                               const float* __restrict__ gg, const float* __restrict__ bb,
                               float invN, int total, int cmask) {
    int e = blockIdx.x * blockDim.x + threadIdx.x;
    if (e >= total) return;
    int c = e & cmask;
    float mean = g_sum[c] * invN;
    float var  = g_sumsq[c] * invN - mean * mean;
    float s = rsqrtf(var + EPSv) * gg[c];
    float v = (x[e] - mean) * s + bb[c];
    y[e] = fmaxf(v, 0.f);
}

// ---------------- orchestration ----------------
extern "C" void kernel_launch(void* const* d_in, const int* in_sizes, int n_in,
                              void* d_out, int out_size) {
    const float* x_feats = (const float*)d_in[0];
    const float* w1a = (const float*)d_in[1];
    const float* w1b = (const float*)d_in[2];
    const float* w1c = (const float*)d_in[3];
    const float* w2  = (const float*)d_in[4];
    const float* w3a = (const float*)d_in[5];
    const float* w3b = (const float*)d_in[6];
    const float* bn1b_g = (const float*)d_in[7];
    const float* bn1b_b = (const float*)d_in[8];
    const float* bn1c_g = (const float*)d_in[9];
    const float* bn1c_b = (const float*)d_in[10];
    const float* bn3a_g = (const float*)d_in[11];
    const float* bn3a_b = (const float*)d_in[12];
    const float* bn3b_g = (const float*)d_in[13];
    const float* bn3b_b = (const float*)d_in[14];
    const int* km1a_in  = (const int*)d_in[15];
    const int* km1a_out = (const int*)d_in[16];
    const int* km1b_in  = (const int*)d_in[17];
    const int* km1b_out = (const int*)d_in[18];
    const int* km1c_in  = (const int*)d_in[19];
    const int* km1c_out = (const int*)d_in[20];
    const int* km2_in   = (const int*)d_in[21];
    const int* km2_out  = (const int*)d_in[22];
    const int* km3a_in  = (const int*)d_in[23];
    const int* km3a_out = (const int*)d_in[24];
    const int* km3b_in  = (const int*)d_in[25];
    const int* km3b_out = (const int*)d_in[26];

    float* out = (float*)d_out;
    float* x_e1 = out;
    float* x_e2 = out + (size_t)N1v * 32;

    float *buf1, *buf2, *buf3, *buf4, *buf5;
    __nv_bfloat16* wf;
    cudaGetSymbolAddress((void**)&buf1, g_buf1);
    cudaGetSymbolAddress((void**)&buf2, g_buf2);
    cudaGetSymbolAddress((void**)&buf3, g_buf3);
    cudaGetSymbolAddress((void**)&buf4, g_buf4);
    cudaGetSymbolAddress((void**)&buf5, g_buf5);
    cudaGetSymbolAddress((void**)&wf, g_wfrag);

    // ---- weight prep (fragment pack + bf16 split) ----
    {
        int t1 = K5v * 32 * 32, t2 = K3v * 32 * 64, t3 = K3v * 64 * 128, t4 = K3v * 128 * 256;
        wprep_frag<<<(t1 + 255) / 256, 256>>>(w1b, wf + (size_t)OFF_W1B * 8, 32, 32, t1);
        wprep_frag<<<(t1 + 255) / 256, 256>>>(w1c, wf + (size_t)OFF_W1C * 8, 32, 32, t1);
        wprep_frag<<<(t2 + 255) / 256, 256>>>(w2,  wf + (size_t)OFF_W2  * 8, 32, 64, t2);
        wprep_frag<<<(t3 + 255) / 256, 256>>>(w3a, wf + (size_t)OFF_W3A * 8, 64, 128, t3);
        wprep_frag<<<(t4 + 255) / 256, 256>>>(w3b, wf + (size_t)OFF_W3B * 8, 128, 256, t4);
    }

    const int SG = 1024;

    // ---- enc1a: conv(1->32, k5) + relu ----
    cudaMemsetAsync(buf1, 0, (size_t)N1v * 32 * sizeof(float), 0);
    {
        int total = K5v * M1v;
        conv1a_kernel<<<(total * 8 + 255) / 256, 256>>>(x_feats, w1a, km1a_in, km1a_out, buf1, total, M1v);
        relu_kernel<<<(N1v * 32 / 4 + 255) / 256, 256>>>(buf1, N1v * 32 / 4);
    }

    // ---- enc1b: conv(32->32, k5) + BN + relu ----
    cudaMemsetAsync(buf2, 0, (size_t)N1v * 32 * sizeof(float), 0);
    spconv_mma<32, 32, 32><<<dim3((M2v + 127) / 128, 1, K5v), 256>>>(
        buf1, wf + (size_t)OFF_W1B * 8, km1b_in, km1b_out, buf2, M2v);
    zero_stats_kernel<<<1, 256>>>();
    bn_stats2<32><<<SG, 256>>>(buf2, N1v);
    bn_relu_kernel<<<(N1v * 32 + 255) / 256, 256>>>(buf2, buf1, bn1b_g, bn1b_b, 1.0f / N1v, N1v * 32, 31);

    // ---- enc1c: conv(32->32, k5) + BN + relu -> x_e1 ----
    cudaMemsetAsync(buf2, 0, (size_t)N1v * 32 * sizeof(float), 0);
    spconv_mma<32, 32, 32><<<dim3((M2v + 127) / 128, 1, K5v), 256>>>(
        buf1, wf + (size_t)OFF_W1C * 8, km1c_in, km1c_out, buf2, M2v);
    zero_stats_kernel<<<1, 256>>>();
    bn_stats2<32><<<SG, 256>>>(buf2, N1v);
    bn_relu_kernel<<<(N1v * 32 + 255) / 256, 256>>>(buf2, x_e1, bn1c_g, bn1c_b, 1.0f / N1v, N1v * 32, 31);

    // ---- conv2: conv(32->64, k3), no activation ----
    cudaMemsetAsync(buf3, 0, (size_t)N2v * 64 * sizeof(float), 0);
    spconv_mma<32, 64, 64><<<dim3((M3v + 127) / 128, 1, K3v), 256>>>(
        x_e1, wf + (size_t)OFF_W2 * 8, km2_in, km2_out, buf3, M3v);

    // ---- enc2a: conv(64->128, k3) + BN + relu ----
    cudaMemsetAsync(buf4, 0, (size_t)N2v * 128 * sizeof(float), 0);
    spconv_mma<64, 128, 128><<<dim3((M4v + 127) / 128, 1, K3v), 256>>>(
        buf3, wf + (size_t)OFF_W3A * 8, km3a_in, km3a_out, buf4, M4v);
    zero_stats_kernel<<<1, 256>>>();
    bn_stats2<128><<<SG, 256>>>(buf4, N2v);
    bn_relu_kernel<<<(N2v * 128 + 255) / 256, 256>>>(buf4, buf4, bn3a_g, bn3a_b, 1.0f / N2v, N2v * 128, 127);

    // ---- enc2b: conv(128->256, k3) + BN + relu -> x_e2 ----
    cudaMemsetAsync(buf5, 0, (size_t)N2v * 256 * sizeof(float), 0);
    spconv_mma<128, 256, 128><<<dim3((M4v + 127) / 128, 2, K3v), 256>>>(
        buf4, wf + (size_t)OFF_W3B * 8, km3b_in, km3b_out, buf5, M4v);
    zero_stats_kernel<<<1, 256>>>();
    bn_stats2<256><<<SG, 256>>>(buf5, N2v);
    bn_relu_kernel<<<(N2v * 256 + 255) / 256, 256>>>(buf5, x_e2, bn3b_g, bn3b_b, 1.0f / N2v, N2v * 256, 255);
}

// round 5
// speedup vs baseline: 1.8399x; 1.2783x over previous
#include <cuda_runtime.h>
#include <cuda_bf16.h>
#include <cstdint>

// ---------------- problem constants ----------------
#define N0v 200000
#define N1v 100000
#define N2v 80000
#define K5v 125
#define K3v 27
#define M1v 20000
#define M2v 20000
#define M3v 30000
#define M4v 20000
#define EPSv 1e-5f

// ---------------- scratch (device globals; no allocs allowed) ----------------
__device__ float g_buf1[N1v * 32];
__device__ float g_buf2[N1v * 32];
__device__ float g_buf3[N2v * 64];
__device__ float g_buf4[N2v * 128];
__device__ float g_buf5[N2v * 256];
__device__ float g_sum[256];
__device__ float g_sumsq[256];

// fragment-packed bf16-split weights (uint4 per lane: b0_hi,b1_hi,b0_lo,b1_lo)
#define OFF_W1B 0
#define OFF_W1C 32000
#define OFF_W2  64000
#define OFF_W3A 77824
#define OFF_W3B 133120
#define WFRAG_U4 354304
__device__ __align__(16) __nv_bfloat16 g_wfrag[WFRAG_U4 * 8];

// ---------------- small helpers ----------------
__device__ __forceinline__ void red4(float* p, float a, float b, float c, float d) {
    asm volatile("red.global.add.v4.f32 [%0], {%1,%2,%3,%4};"
                 :: "l"(p), "f"(a), "f"(b), "f"(c), "f"(d) : "memory");
}

// bf16 m16n8k16 mma: D += A * B (row.col, f32 accum)
__device__ __forceinline__ void mma16(float* d, const uint32_t* a, uint32_t b0, uint32_t b1) {
    asm volatile(
        "mma.sync.aligned.m16n8k16.row.col.f32.bf16.bf16.f32 "
        "{%0,%1,%2,%3}, {%4,%5,%6,%7}, {%8,%9}, {%0,%1,%2,%3};"
        : "+f"(d[0]), "+f"(d[1]), "+f"(d[2]), "+f"(d[3])
        : "r"(a[0]), "r"(a[1]), "r"(a[2]), "r"(a[3]), "r"(b0), "r"(b1));
}

// ---------------- weight prep: transpose + bf16 split + fragment pack ----------------
__global__ void wprep_frag(const float* __restrict__ w, __nv_bfloat16* __restrict__ frag,
                           int CIN, int COUT, int total) {
    int e = blockIdx.x * blockDim.x + threadIdx.x;
    if (e >= total) return;
    int per = CIN * COUT;
    int k = e / per;
    int r = e - k * per;
    int ci = r / COUT;
    int co = r - ci * COUT;
    float v = w[e];
    __nv_bfloat16 h = __float2bfloat16(v);
    __nv_bfloat16 l = __float2bfloat16(v - __bfloat162float(h));
    int lane = ((co & 7) << 2) | ((ci & 7) >> 1);
    size_t f4 = (((size_t)k * (CIN >> 4) + (ci >> 4)) * (COUT >> 3) + (co >> 3)) * 32 + lane;
    int within = ci & 15;
    int slot = ((within >> 3) << 1) | (within & 1);
    frag[f4 * 8 + slot] = h;
    frag[f4 * 8 + 4 + slot] = l;
}

// ---------------- conv1a: CIN=1 special case (fp32 scalar) ----------------
__global__ void conv1a_kernel(const float* __restrict__ x, const float* __restrict__ w,
                              const int* __restrict__ in_idx, const int* __restrict__ out_idx,
                              float* __restrict__ out, int total, int M) {
    int gid = blockIdx.x * blockDim.x + threadIdx.x;
    int pair = gid >> 3;
    if (pair >= total) return;
    int g = gid & 7;
    int k = pair / M;
    float v = x[in_idx[pair]];
    float4 wv = *reinterpret_cast<const float4*>(w + k * 32 + g * 4);
    float* dst = out + (size_t)out_idx[pair] * 32 + g * 4;
    red4(dst, v * wv.x, v * wv.y, v * wv.z, v * wv.w);
}

// ---------------- bf16x3 gather-MMA-scatter, pipelined ----------------
template<int CIN, int COUT, int BN>
__global__ __launch_bounds__(256, 2)
void spconv_mma(const float* __restrict__ feats, const __nv_bfloat16* __restrict__ wfrag,
                const int* __restrict__ in_idx, const int* __restrict__ out_idx,
                float* __restrict__ out, int M) {
    constexpr int NT  = BN / 8;
    constexpr int NTG = COUT / 8;
    constexpr int NCH = CIN / 32;

    __shared__ uint32_t As_h[2][128][20];   // double-buffered, stride20 = conflict-free
    __shared__ uint32_t As_l[2][128][20];
    __shared__ int rows[128];

    const int k    = blockIdx.z;
    const int m0   = blockIdx.x * 128;
    const int n0   = blockIdx.y * BN;
    const int tid  = threadIdx.x;
    const int wid  = tid >> 5;
    const int lane = tid & 31;

    if (tid < 128) {
        int m = m0 + tid;
        rows[tid] = (m < M) ? in_idx[k * M + m] : -1;
    }
    __syncthreads();

    const int mrow = tid >> 1;
    const int frow = rows[mrow];
    const int half = tid & 1;
    const float* fbase = (frow >= 0) ? (feats + (size_t)frow * CIN + half * 16) : feats;

    float acc[NT][4];
#pragma unroll
    for (int nt = 0; nt < NT; nt++) {
        acc[nt][0] = 0.f; acc[nt][1] = 0.f; acc[nt][2] = 0.f; acc[nt][3] = 0.f;
    }

    const uint4* wbase = reinterpret_cast<const uint4*>(wfrag)
                       + ((size_t)k * (CIN >> 4)) * NTG * 32;
    const int gr = lane >> 2;
    const int gc = lane & 3;
    const int r0 = wid * 16 + gr;

    float4 pf[4];
    // prologue: gather chunk 0 into regs
    if (frow >= 0) {
        const float4* s = reinterpret_cast<const float4*>(fbase);
        pf[0] = s[0]; pf[1] = s[1]; pf[2] = s[2]; pf[3] = s[3];
    }
    // convert + store chunk 0 -> buffer 0
    {
        uint32_t* dh = &As_h[0][mrow][half * 8];
        uint32_t* dl = &As_l[0][mrow][half * 8];
        if (frow >= 0) {
#pragma unroll
            for (int j = 0; j < 4; j++) {
                float4 v = pf[j];
                __nv_bfloat162 h01 = __floats2bfloat162_rn(v.x, v.y);
                __nv_bfloat162 h23 = __floats2bfloat162_rn(v.z, v.w);
                __nv_bfloat162 l01 = __floats2bfloat162_rn(
                    v.x - __bfloat162float(h01.x), v.y - __bfloat162float(h01.y));
                __nv_bfloat162 l23 = __floats2bfloat162_rn(
                    v.z - __bfloat162float(h23.x), v.w - __bfloat162float(h23.y));
                dh[j * 2]     = *reinterpret_cast<uint32_t*>(&h01);
                dh[j * 2 + 1] = *reinterpret_cast<uint32_t*>(&h23);
                dl[j * 2]     = *reinterpret_cast<uint32_t*>(&l01);
                dl[j * 2 + 1] = *reinterpret_cast<uint32_t*>(&l23);
            }
        } else {
#pragma unroll
            for (int j = 0; j < 8; j++) { dh[j] = 0u; dl[j] = 0u; }
        }
    }
    __syncthreads();

#pragma unroll
    for (int c = 0; c < NCH; c++) {
        const int cb = c & 1;
        // prefetch next chunk into regs (latency hidden behind MMA below)
        if (c + 1 < NCH && frow >= 0) {
            const float4* s = reinterpret_cast<const float4*>(fbase + (c + 1) * 32);
            pf[0] = s[0]; pf[1] = s[1]; pf[2] = s[2]; pf[3] = s[3];
        }

#pragma unroll
        for (int s = 0; s < 2; s++) {
            const int kb = s * 8;
            uint32_t aH[4], aL[4];
            aH[0] = As_h[cb][r0][kb + gc];
            aH[1] = As_h[cb][r0 + 8][kb + gc];
            aH[2] = As_h[cb][r0][kb + 4 + gc];
            aH[3] = As_h[cb][r0 + 8][kb + 4 + gc];
            aL[0] = As_l[cb][r0][kb + gc];
            aL[1] = As_l[cb][r0 + 8][kb + gc];
            aL[2] = As_l[cb][r0][kb + 4 + gc];
            aL[3] = As_l[cb][r0 + 8][kb + 4 + gc];

            const uint4* wrow = wbase + ((size_t)(c * 2 + s) * NTG + (n0 >> 3)) * 32 + lane;
#pragma unroll
            for (int ng = 0; ng < NT; ng += 4) {
                uint4 b0 = wrow[(ng + 0) * 32];
                uint4 b1 = wrow[(ng + 1) * 32];
                uint4 b2 = wrow[(ng + 2) * 32];
                uint4 b3 = wrow[(ng + 3) * 32];
                // term 1: hi*hi — 4 independent accumulator chains
                mma16(acc[ng + 0], aH, b0.x, b0.y);
                mma16(acc[ng + 1], aH, b1.x, b1.y);
                mma16(acc[ng + 2], aH, b2.x, b2.y);
                mma16(acc[ng + 3], aH, b3.x, b3.y);
                // term 2: lo*hi
                mma16(acc[ng + 0], aL, b0.x, b0.y);
                mma16(acc[ng + 1], aL, b1.x, b1.y);
                mma16(acc[ng + 2], aL, b2.x, b2.y);
                mma16(acc[ng + 3], aL, b3.x, b3.y);
                // term 3: hi*lo
                mma16(acc[ng + 0], aH, b0.z, b0.w);
                mma16(acc[ng + 1], aH, b1.z, b1.w);
                mma16(acc[ng + 2], aH, b2.z, b2.w);
                mma16(acc[ng + 3], aH, b3.z, b3.w);
            }
        }

        // convert + store next chunk into other buffer
        if (c + 1 < NCH) {
            const int nb = (c + 1) & 1;
            uint32_t* dh = &As_h[nb][mrow][half * 8];
            uint32_t* dl = &As_l[nb][mrow][half * 8];
            if (frow >= 0) {
#pragma unroll
                for (int j = 0; j < 4; j++) {
                    float4 v = pf[j];
                    __nv_bfloat162 h01 = __floats2bfloat162_rn(v.x, v.y);
                    __nv_bfloat162 h23 = __floats2bfloat162_rn(v.z, v.w);
                    __nv_bfloat162 l01 = __floats2bfloat162_rn(
                        v.x - __bfloat162float(h01.x), v.y - __bfloat162float(h01.y));
                    __nv_bfloat162 l23 = __floats2bfloat162_rn(
                        v.z - __bfloat162float(h23.x), v.w - __bfloat162float(h23.y));
                    dh[j * 2]     = *reinterpret_cast<uint32_t*>(&h01);
                    dh[j * 2 + 1] = *reinterpret_cast<uint32_t*>(&h23);
                    dl[j * 2]     = *reinterpret_cast<uint32_t*>(&l01);
                    dl[j * 2 + 1] = *reinterpret_cast<uint32_t*>(&l23);
                }
            } else {
#pragma unroll
                for (int j = 0; j < 8; j++) { dh[j] = 0u; dl[j] = 0u; }
            }
            __syncthreads();
        }
    }

    // ---- scatter: pair lanes via shfl to form contiguous red4 ----
    const int mA = m0 + r0;
    const int mB = mA + 8;
    const int oA = (mA < M) ? out_idx[k * M + mA] : -1;
    const int oB = (mB < M) ? out_idx[k * M + mB] : -1;
    float* dA0 = out + (oA >= 0 ? (size_t)oA * COUT : 0) + n0;
    float* dB0 = out + (oB >= 0 ? (size_t)oB * COUT : 0) + n0;
    const bool even = (gc & 1) == 0;

#pragma unroll
    for (int nt = 0; nt < NT; nt += 2) {
        float sA0 = even ? acc[nt + 1][0] : acc[nt][0];
        float sA1 = even ? acc[nt + 1][1] : acc[nt][1];
        float sB0 = even ? acc[nt + 1][2] : acc[nt][2];
        float sB1 = even ? acc[nt + 1][3] : acc[nt][3];
        float rA0 = __shfl_xor_sync(0xffffffffu, sA0, 1);
        float rA1 = __shfl_xor_sync(0xffffffffu, sA1, 1);
        float rB0 = __shfl_xor_sync(0xffffffffu, sB0, 1);
        float rB1 = __shfl_xor_sync(0xffffffffu, sB1, 1);
        int myt = even ? nt : nt + 1;
        int cbase = myt * 8 + (even ? 2 * gc : 2 * gc - 2);
        float a0 = even ? acc[nt][0] : rA0;
        float a1 = even ? acc[nt][1] : rA1;
        float a2 = even ? rA0 : acc[nt + 1][0];
        float a3 = even ? rA1 : acc[nt + 1][1];
        float b0 = even ? acc[nt][2] : rB0;
        float b1 = even ? acc[nt][3] : rB1;
        float b2 = even ? rB0 : acc[nt + 1][2];
        float b3 = even ? rB1 : acc[nt + 1][3];
        if (oA >= 0) red4(dA0 + cbase, a0, a1, a2, a3);
        if (oB >= 0) red4(dB0 + cbase, b0, b1, b2, b3);
    }
}

// ---------------- elementwise / BN kernels ----------------
__global__ void relu_kernel(float* __restrict__ x, int n4) {
    int i = blockIdx.x * blockDim.x + threadIdx.x;
    if (i >= n4) return;
    float4 v = reinterpret_cast<float4*>(x)[i];
    v.x = fmaxf(v.x, 0.f); v.y = fmaxf(v.y, 0.f);
    v.z = fmaxf(v.z, 0.f); v.w = fmaxf(v.w, 0.f);
    reinterpret_cast<float4*>(x)[i] = v;
}

__global__ void zero_stats_kernel() {
    g_sum[threadIdx.x] = 0.f;
    g_sumsq[threadIdx.x] = 0.f;
}

// atomic-free per-thread channel accumulation
template<int C>
__global__ void bn_stats2(const float* __restrict__ x, int rows) {
    constexpr int RPB = 256 / C;
    const int c = threadIdx.x & (C - 1);
    const int rsub = threadIdx.x / C;
    float s = 0.f, q = 0.f;
    for (int r = blockIdx.x * RPB + rsub; r < rows; r += gridDim.x * RPB) {
        float v = x[(size_t)r * C + c];
        s += v; q += v * v;
    }
    __shared__ float ss[256], sq[256];
    ss[threadIdx.x] = s; sq[threadIdx.x] = q;
    __syncthreads();
    if (threadIdx.x < C) {
        for (int j = threadIdx.x + C; j < 256; j += C) { s += ss[j]; q += sq[j]; }
        atomicAdd(&g_sum[c], s);
        atomicAdd(&g_sumsq[c], q);
    }
}

__global__ void bn_relu_kernel(const float* __restrict__ x, float* __restrict__ y,
                               const float* __restrict__ gg, const float* __restrict__ bb,
                               float invN, int total, int cmask) {
    int e = blockIdx.x * blockDim.x + threadIdx.x;
    if (e >= total) return;
    int c = e & cmask;
    float mean = g_sum[c] * invN;
    float var  = g_sumsq[c] * invN - mean * mean;
    float s = rsqrtf(var + EPSv) * gg[c];
    float v = (x[e] - mean) * s + bb[c];
    y[e] = fmaxf(v, 0.f);
}

// ---------------- orchestration ----------------
extern "C" void kernel_launch(void* const* d_in, const int* in_sizes, int n_in,
                              void* d_out, int out_size) {
    const float* x_feats = (const float*)d_in[0];
    const float* w1a = (const float*)d_in[1];
    const float* w1b = (const float*)d_in[2];
    const float* w1c = (const float*)d_in[3];
    const float* w2  = (const float*)d_in[4];
    const float* w3a = (const float*)d_in[5];
    const float* w3b = (const float*)d_in[6];
    const float* bn1b_g = (const float*)d_in[7];
    const float* bn1b_b = (const float*)d_in[8];
    const float* bn1c_g = (const float*)d_in[9];
    const float* bn1c_b = (const float*)d_in[10];
    const float* bn3a_g = (const float*)d_in[11];
    const float* bn3a_b = (const float*)d_in[12];
    const float* bn3b_g = (const float*)d_in[13];
    const float* bn3b_b = (const float*)d_in[14];
    const int* km1a_in  = (const int*)d_in[15];
    const int* km1a_out = (const int*)d_in[16];
    const int* km1b_in  = (const int*)d_in[17];
    const int* km1b_out = (const int*)d_in[18];
    const int* km1c_in  = (const int*)d_in[19];
    const int* km1c_out = (const int*)d_in[20];
    const int* km2_in   = (const int*)d_in[21];
    const int* km2_out  = (const int*)d_in[22];
    const int* km3a_in  = (const int*)d_in[23];
    const int* km3a_out = (const int*)d_in[24];
    const int* km3b_in  = (const int*)d_in[25];
    const int* km3b_out = (const int*)d_in[26];

    float* out = (float*)d_out;
    float* x_e1 = out;
    float* x_e2 = out + (size_t)N1v * 32;

    float *buf1, *buf2, *buf3, *buf4, *buf5;
    __nv_bfloat16* wf;
    cudaGetSymbolAddress((void**)&buf1, g_buf1);
    cudaGetSymbolAddress((void**)&buf2, g_buf2);
    cudaGetSymbolAddress((void**)&buf3, g_buf3);
    cudaGetSymbolAddress((void**)&buf4, g_buf4);
    cudaGetSymbolAddress((void**)&buf5, g_buf5);
    cudaGetSymbolAddress((void**)&wf, g_wfrag);

    // ---- weight prep (fragment pack + bf16 split) ----
    {
        int t1 = K5v * 32 * 32, t2 = K3v * 32 * 64, t3 = K3v * 64 * 128, t4 = K3v * 128 * 256;
        wprep_frag<<<(t1 + 255) / 256, 256>>>(w1b, wf + (size_t)OFF_W1B * 8, 32, 32, t1);
        wprep_frag<<<(t1 + 255) / 256, 256>>>(w1c, wf + (size_t)OFF_W1C * 8, 32, 32, t1);
        wprep_frag<<<(t2 + 255) / 256, 256>>>(w2,  wf + (size_t)OFF_W2  * 8, 32, 64, t2);
        wprep_frag<<<(t3 + 255) / 256, 256>>>(w3a, wf + (size_t)OFF_W3A * 8, 64, 128, t3);
        wprep_frag<<<(t4 + 255) / 256, 256>>>(w3b, wf + (size_t)OFF_W3B * 8, 128, 256, t4);
    }

    const int SG = 1024;

    // ---- enc1a: conv(1->32, k5) + relu ----
    cudaMemsetAsync(buf1, 0, (size_t)N1v * 32 * sizeof(float), 0);
    {
        int total = K5v * M1v;
        conv1a_kernel<<<(total * 8 + 255) / 256, 256>>>(x_feats, w1a, km1a_in, km1a_out, buf1, total, M1v);
        relu_kernel<<<(N1v * 32 / 4 + 255) / 256, 256>>>(buf1, N1v * 32 / 4);
    }

    // ---- enc1b: conv(32->32, k5) + BN + relu ----
    cudaMemsetAsync(buf2, 0, (size_t)N1v * 32 * sizeof(float), 0);
    spconv_mma<32, 32, 32><<<dim3((M2v + 127) / 128, 1, K5v), 256>>>(
        buf1, wf + (size_t)OFF_W1B * 8, km1b_in, km1b_out, buf2, M2v);
    zero_stats_kernel<<<1, 256>>>();
    bn_stats2<32><<<SG, 256>>>(buf2, N1v);
    bn_relu_kernel<<<(N1v * 32 + 255) / 256, 256>>>(buf2, buf1, bn1b_g, bn1b_b, 1.0f / N1v, N1v * 32, 31);

    // ---- enc1c: conv(32->32, k5) + BN + relu -> x_e1 ----
    cudaMemsetAsync(buf2, 0, (size_t)N1v * 32 * sizeof(float), 0);
    spconv_mma<32, 32, 32><<<dim3((M2v + 127) / 128, 1, K5v), 256>>>(
        buf1, wf + (size_t)OFF_W1C * 8, km1c_in, km1c_out, buf2, M2v);
    zero_stats_kernel<<<1, 256>>>();
    bn_stats2<32><<<SG, 256>>>(buf2, N1v);
    bn_relu_kernel<<<(N1v * 32 + 255) / 256, 256>>>(buf2, x_e1, bn1c_g, bn1c_b, 1.0f / N1v, N1v * 32, 31);

    // ---- conv2: conv(32->64, k3), no activation ----
    cudaMemsetAsync(buf3, 0, (size_t)N2v * 64 * sizeof(float), 0);
    spconv_mma<32, 64, 64><<<dim3((M3v + 127) / 128, 1, K3v), 256>>>(
        x_e1, wf + (size_t)OFF_W2 * 8, km2_in, km2_out, buf3, M3v);

    // ---- enc2a: conv(64->128, k3) + BN + relu ----
    cudaMemsetAsync(buf4, 0, (size_t)N2v * 128 * sizeof(float), 0);
    spconv_mma<64, 128, 128><<<dim3((M4v + 127) / 128, 1, K3v), 256>>>(
        buf3, wf + (size_t)OFF_W3A * 8, km3a_in, km3a_out, buf4, M4v);
    zero_stats_kernel<<<1, 256>>>();
    bn_stats2<128><<<SG, 256>>>(buf4, N2v);
    bn_relu_kernel<<<(N2v * 128 + 255) / 256, 256>>>(buf4, buf4, bn3a_g, bn3a_b, 1.0f / N2v, N2v * 128, 127);

    // ---- enc2b: conv(128->256, k3) + BN + relu -> x_e2 ----
    cudaMemsetAsync(buf5, 0, (size_t)N2v * 256 * sizeof(float), 0);
    spconv_mma<128, 256, 128><<<dim3((M4v + 127) / 128, 2, K3v), 256>>>(
        buf4, wf + (size_t)OFF_W3B * 8, km3b_in, km3b_out, buf5, M4v);
    zero_stats_kernel<<<1, 256>>>();
    bn_stats2<256><<<SG, 256>>>(buf5, N2v);
    bn_relu_kernel<<<(N2v * 256 + 255) / 256, 256>>>(buf5, x_e2, bn3b_g, bn3b_b, 1.0f / N2v, N2v * 256, 255);
}